// round 16
// baseline (speedup 1.0000x reference)
#include <cuda_runtime.h>
#include <cuda_bf16.h>
#include <math.h>
#include <stdint.h>

// Problem dims
#define BB 2
#define TT 2048
#define BT 4096          // B*T
#define EE 1024
#define HH 16
#define DD 64
#define VV 32000
#define KT 16            // K-chunks of 64 over K=1024 (tcgen05 path)

// Arch-path selection: TC_PATH=1 only in arch-/family-specific device passes
// (tcgen05 + f32x2 legal). Plain compute_103/sm_103 passes compile fallbacks.
#if defined(__CUDA_ARCH__) && (defined(__CUDA_ARCH_FEAT_SM103_ALL) || \
    defined(__CUDA_ARCH_SPECIFIC__) || defined(__CUDA_ARCH_FAMILY_SPECIFIC__))
#define TC_PATH 1
#else
#define TC_PATH 0
#endif

// ---------------------------------------------------------------------------
// Fast exp on the FMA pipe (no MUFU). exp(x) = 2^(x*log2e); round via the
// 1.5*2^23 magic constant (RN add does the rounding, integer recovered with
// one IADD on the float bits), degree-5 Taylor for 2^f on [-0.5,0.5]
// (rel err ~2e-6), exponent splice via IADD+SHL. Args <= 0 here; x = -inf
// clamps to 2^-126 ~ 1.2e-38 (effectively 0, never NaN), preserving the
// -INFINITY masking semantics.
// ---------------------------------------------------------------------------
__device__ __forceinline__ float fast_exp(float x) {
    float t = x * 1.4426950408889634f;
    t = fminf(fmaxf(t, -126.0f), 126.0f);
    float z = t + 12582912.0f;                       // 1.5 * 2^23
    int   n = __float_as_int(z) - 0x4B400000;        // round-to-nearest int
    float f = t - (z - 12582912.0f);                 // f in [-0.5, 0.5]
    float p = 0.00133335581f;
    p = fmaf(p, f, 0.00961804886f);
    p = fmaf(p, f, 0.0555041087f);
    p = fmaf(p, f, 0.240226507f);
    p = fmaf(p, f, 0.693147180f);
    p = fmaf(p, f, 1.0f);
    return __int_as_float(__float_as_int(p) + (n << 23));
}

// ---------------------------------------------------------------------------
// Scratch (static device globals)
// ---------------------------------------------------------------------------
__device__ float g_X[BT * EE];
__device__ float g_Q[BT * EE];
__device__ float g_Kb[BT * EE];
__device__ float g_Vb[BT * EE];
__device__ float g_O[BT * EE];
__device__ float g_rowloss[BT];

// bf16 hi/lo operands as pre-swizzled SW128 tiles (128 rows x 64 cols = 16KB)
__device__ __nv_bfloat16 g_Xh[BT * EE],  g_Xl[BT * EE];
__device__ __nv_bfloat16 g_Oh[BT * EE],  g_Ol[BT * EE];
__device__ __nv_bfloat16 g_Wqh[EE * EE], g_Wql[EE * EE];
__device__ __nv_bfloat16 g_Wkh[EE * EE], g_Wkl[EE * EE];
__device__ __nv_bfloat16 g_Wvh[EE * EE], g_Wvl[EE * EE];
__device__ __nv_bfloat16 g_Woh[(size_t)VV * EE], g_Wol[(size_t)VV * EE];

// ---------------------------------------------------------------------------
// tcgen05 / bulk-async helpers (arch-specific pass only)
// ---------------------------------------------------------------------------
#if TC_PATH
__device__ __forceinline__ uint32_t smem_u32(const void* p) {
    uint32_t a;
    asm("{ .reg .u64 t; cvta.to.shared.u64 t, %1; cvt.u32.u64 %0, t; }"
        : "=r"(a) : "l"(p));
    return a;
}
__device__ __forceinline__ uint64_t sw128_desc(uint32_t addr) {
    const uint64_t base = (uint64_t(2) << 61) | (uint64_t(1) << 46)
                        | (uint64_t(64) << 32) | (uint64_t(1) << 16);
    return base | ((uint64_t)(addr >> 4) & 0x3FFF);
}
__device__ __forceinline__ void tc_alloc(uint32_t smem_res, uint32_t ncols) {
    asm volatile("tcgen05.alloc.cta_group::1.sync.aligned.shared::cta.b32 [%0], %1;"
                 :: "r"(smem_res), "r"(ncols) : "memory");
}
__device__ __forceinline__ void tc_relinquish() {
    asm volatile("tcgen05.relinquish_alloc_permit.cta_group::1.sync.aligned;");
}
__device__ __forceinline__ void tc_dealloc(uint32_t tmem, uint32_t ncols) {
    asm volatile("tcgen05.dealloc.cta_group::1.sync.aligned.b32 %0, %1;"
                 :: "r"(tmem), "r"(ncols));
}
__device__ __forceinline__ void mbar_init(uint32_t mb, uint32_t cnt) {
    asm volatile("mbarrier.init.shared.b64 [%0], %1;" :: "r"(mb), "r"(cnt) : "memory");
}
__device__ __forceinline__ void mbar_expect_tx(uint32_t mb, uint32_t bytes) {
    asm volatile("mbarrier.arrive.expect_tx.shared.b64 _, [%0], %1;"
                 :: "r"(mb), "r"(bytes) : "memory");
}
__device__ __forceinline__ void tc_commit(uint32_t mb) {
    asm volatile("tcgen05.commit.cta_group::1.mbarrier::arrive::one.shared::cluster.b64 [%0];"
                 :: "r"(mb) : "memory");
}
__device__ __forceinline__ void mbar_wait(uint32_t mb, uint32_t parity) {
    uint32_t done;
    asm volatile("{\n\t.reg .pred p;\n\t"
                 "mbarrier.try_wait.parity.acquire.cta.shared::cta.b64 p, [%1], %2;\n\t"
                 "selp.b32 %0, 1, 0, p;\n\t}"
                 : "=r"(done) : "r"(mb), "r"(parity) : "memory");
    while (!done) {
        asm volatile("{\n\t.reg .pred p;\n\t"
                     "mbarrier.try_wait.parity.acquire.cta.shared::cta.b64 p, [%1], %2, 0x989680;\n\t"
                     "selp.b32 %0, 1, 0, p;\n\t}"
                     : "=r"(done) : "r"(mb), "r"(parity) : "memory");
    }
}
__device__ __forceinline__ void bulk_cp(uint32_t dst, const void* src,
                                        uint32_t bytes, uint32_t mb) {
    asm volatile("cp.async.bulk.shared::cta.global.mbarrier::complete_tx::bytes "
                 "[%0], [%1], %2, [%3];"
                 :: "r"(dst), "l"(src), "r"(bytes), "r"(mb) : "memory");
}
__device__ __forceinline__ void tc_fence_after() {
    asm volatile("tcgen05.fence::after_thread_sync;" ::: "memory");
}
__device__ __forceinline__ void tc_fence_before() {
    asm volatile("tcgen05.fence::before_thread_sync;" ::: "memory");
}
__device__ __forceinline__ void tc_wait_ld() {
    asm volatile("tcgen05.wait::ld.sync.aligned;" ::: "memory");
}
__device__ __forceinline__ void mma_ss_bf16(uint32_t d_tmem, uint64_t a_desc,
                                            uint64_t b_desc, uint32_t idesc,
                                            uint32_t en) {
    asm volatile(
        "{\n\t"
        ".reg .pred p;\n\t"
        "setp.ne.u32 p, %5, 0;\n\t"
        "tcgen05.mma.cta_group::1.kind::f16 [%0], %1, %2, %3, {%4, %4, %4, %4}, p;\n\t"
        "}"
        :: "r"(d_tmem), "l"(a_desc), "l"(b_desc), "r"(idesc), "r"(0u), "r"(en)
        : "memory");
}
__device__ __forceinline__ void ldtm_x32(uint32_t* r, uint32_t tmem_addr) {
    asm volatile(
        "tcgen05.ld.sync.aligned.32x32b.x32.b32 "
        "{%0, %1, %2, %3, %4, %5, %6, %7, "
        " %8, %9, %10, %11, %12, %13, %14, %15, "
        " %16, %17, %18, %19, %20, %21, %22, %23, "
        " %24, %25, %26, %27, %28, %29, %30, %31}, [%32];"
        : "=r"(r[0]),  "=r"(r[1]),  "=r"(r[2]),  "=r"(r[3]),
          "=r"(r[4]),  "=r"(r[5]),  "=r"(r[6]),  "=r"(r[7]),
          "=r"(r[8]),  "=r"(r[9]),  "=r"(r[10]), "=r"(r[11]),
          "=r"(r[12]), "=r"(r[13]), "=r"(r[14]), "=r"(r[15]),
          "=r"(r[16]), "=r"(r[17]), "=r"(r[18]), "=r"(r[19]),
          "=r"(r[20]), "=r"(r[21]), "=r"(r[22]), "=r"(r[23]),
          "=r"(r[24]), "=r"(r[25]), "=r"(r[26]), "=r"(r[27]),
          "=r"(r[28]), "=r"(r[29]), "=r"(r[30]), "=r"(r[31])
        : "r"(tmem_addr));
}
#define MMA_IDESC 0x8200490u   // F32 accum, BF16xBF16, M=128, N=128

// packed f32x2 helpers
typedef unsigned long long ull;
__device__ __forceinline__ void fma2(ull& d, ull a, ull b) {
    asm("fma.rn.f32x2 %0, %1, %2, %3;" : "=l"(d) : "l"(a), "l"(b), "l"(d));
}
__device__ __forceinline__ ull mul2(ull a, ull b) {
    ull d; asm("mul.rn.f32x2 %0, %1, %2;" : "=l"(d) : "l"(a), "l"(b)); return d;
}
__device__ __forceinline__ ull pack2(float lo, float hi) {
    ull r; asm("mov.b64 %0, {%1, %2};" : "=l"(r) : "f"(lo), "f"(hi)); return r;
}
__device__ __forceinline__ void unpack2(float& lo, float& hi, ull v) {
    asm("mov.b64 {%0, %1}, %2;" : "=f"(lo), "=f"(hi) : "l"(v));
}
#endif // TC_PATH

// ---------------------------------------------------------------------------
// 1) Embedding
// ---------------------------------------------------------------------------
__global__ void embed_kernel(const int* __restrict__ tokens,
                             const float* __restrict__ tok_table,
                             const float* __restrict__ pos_emb)
{
    int m   = blockIdx.x;
    int tok = tokens[m];
    int tp  = m % TT;
    const float4* tr = (const float4*)(tok_table + (size_t)tok * EE);
    const float4* pr = (const float4*)(pos_emb  + (size_t)tp  * EE);
    float4* xr = (float4*)(g_X + (size_t)m * EE);
    int i = threadIdx.x;
    float4 a = tr[i];
    float4 b = pr[i];
    xr[i] = make_float4(a.x + b.x, a.y + b.y, a.z + b.z, a.w + b.w);
}

// ---------------------------------------------------------------------------
// 2a) Split f32 [R,1024] into pre-swizzled bf16 hi/lo SW128 tiles (TC path).
// ---------------------------------------------------------------------------
__global__ __launch_bounds__(256)
void split_tiles_kernel(const float* __restrict__ src,
                        __nv_bfloat16* __restrict__ hi,
                        __nv_bfloat16* __restrict__ lo)
{
#if TC_PATH
    int row = blockIdx.x;
    int c4  = threadIdx.x;
    float4 a = ((const float4*)(src + (size_t)row * EE))[c4];

    int mt = row >> 7, r = row & 127;
    int k  = c4 << 2;
    int kc = k >> 6, cc = k & 63;
    size_t tile_byte = ((size_t)mt * KT + kc) * 16384;
    uint32_t boff = (uint32_t)(r * 128 + cc * 2);
    uint32_t sw = boff ^ ((boff >> 3) & 0x70);

    __nv_bfloat16 h0 = __float2bfloat16(a.x);
    __nv_bfloat16 h1 = __float2bfloat16(a.y);
    __nv_bfloat16 h2 = __float2bfloat16(a.z);
    __nv_bfloat16 h3 = __float2bfloat16(a.w);
    __nv_bfloat16 l0 = __float2bfloat16(a.x - __bfloat162float(h0));
    __nv_bfloat16 l1 = __float2bfloat16(a.y - __bfloat162float(h1));
    __nv_bfloat16 l2 = __float2bfloat16(a.z - __bfloat162float(h2));
    __nv_bfloat16 l3 = __float2bfloat16(a.w - __bfloat162float(h3));

    uint2 hp, lp;
    hp.x = (uint32_t)__bfloat16_as_ushort(h0) | ((uint32_t)__bfloat16_as_ushort(h1) << 16);
    hp.y = (uint32_t)__bfloat16_as_ushort(h2) | ((uint32_t)__bfloat16_as_ushort(h3) << 16);
    lp.x = (uint32_t)__bfloat16_as_ushort(l0) | ((uint32_t)__bfloat16_as_ushort(l1) << 16);
    lp.y = (uint32_t)__bfloat16_as_ushort(l2) | ((uint32_t)__bfloat16_as_ushort(l3) << 16);

    *(uint2*)((char*)hi + tile_byte + sw) = hp;
    *(uint2*)((char*)lo + tile_byte + sw) = lp;
#endif
}

// ---------------------------------------------------------------------------
// 2b) tcgen05 bf16-split GEMM (NT). CTA tile 128x256, K-chunk 64, bulk-async
//     double-buffered pipeline driven by thread 0, SS MMA, 3-product split.
//     grid = (M/128, N/256), 128 threads.
// ---------------------------------------------------------------------------
#define GEMM_SMEM 197632   // 1024 header + 2 x 96KB buffers

__global__ __launch_bounds__(128, 1)
void gemm_tc(const __nv_bfloat16* __restrict__ Ah, const __nv_bfloat16* __restrict__ Al,
             const __nv_bfloat16* __restrict__ Bh, const __nv_bfloat16* __restrict__ Bl,
             const float* __restrict__ bias, float* __restrict__ C, int N)
{
#if TC_PATH
    extern __shared__ char sm[];
    uint32_t sb  = smem_u32(sm);
    int tid  = threadIdx.x;
    int wid  = tid >> 5;
    int lane = tid & 31;
    int mt   = blockIdx.x;                // m-tile (fast dim for L2 reuse of A)
    int nt0  = blockIdx.y * 2;
    int m0   = mt * 128;
    int n0   = blockIdx.y * 256;

    uint32_t full0 = sb + 8,  full1 = sb + 16;
    uint32_t emp0  = sb + 24, emp1  = sb + 32;

    if (wid == 0) {
        tc_alloc(sb, 256);
        tc_relinquish();
    }
    if (tid == 0) {
        mbar_init(full0, 1); mbar_init(full1, 1);
        mbar_init(emp0, 1);  mbar_init(emp1, 1);
    }
    __syncthreads();
    uint32_t tmem;
    asm volatile("ld.shared.b32 %0, [%1];" : "=r"(tmem) : "r"(sb));

    if (tid == 0) {
        const char* baAh  = (const char*)Ah + (size_t)mt * KT * 16384;
        const char* baAl  = (const char*)Al + (size_t)mt * KT * 16384;
        const char* baB0h = (const char*)Bh + (size_t)nt0 * KT * 16384;
        const char* baB1h = (const char*)Bh + (size_t)(nt0 + 1) * KT * 16384;
        const char* baB0l = (const char*)Bl + (size_t)nt0 * KT * 16384;
        const char* baB1l = (const char*)Bl + (size_t)(nt0 + 1) * KT * 16384;

        int fph0 = 0, fph1 = 0, eph0 = 0, eph1 = 0;
        for (int c = 0; c < KT; c++) {
            int buf = c & 1;
            uint32_t bb = sb + 1024 + buf * 98304;
            uint32_t full = buf ? full1 : full0;

            if (c >= 2) {                 // buffer free when its prior MMAs done
                if (buf) { mbar_wait(emp1, eph1); eph1 ^= 1; }
                else     { mbar_wait(emp0, eph0); eph0 ^= 1; }
            }

            size_t co = (size_t)c * 16384;
            mbar_expect_tx(full, 98304);
            bulk_cp(bb,         baAh  + co, 16384, full);
            bulk_cp(bb + 16384, baAl  + co, 16384, full);
            bulk_cp(bb + 32768, baB0h + co, 16384, full);
            bulk_cp(bb + 49152, baB1h + co, 16384, full);
            bulk_cp(bb + 65536, baB0l + co, 16384, full);
            bulk_cp(bb + 81920, baB1l + co, 16384, full);

            if (buf) { mbar_wait(full1, fph1); fph1 ^= 1; }
            else     { mbar_wait(full0, fph0); fph0 ^= 1; }

            uint64_t adh  = sw128_desc(bb);
            uint64_t adl  = sw128_desc(bb + 16384);
            uint64_t bdh0 = sw128_desc(bb + 32768);
            uint64_t bdh1 = sw128_desc(bb + 49152);
            uint64_t bdl0 = sw128_desc(bb + 65536);
            uint64_t bdl1 = sw128_desc(bb + 81920);
#pragma unroll
            for (int ks = 0; ks < 4; ks++) {
                uint32_t off = ks * 2;              // 16 bf16 = 32B = 2 units
                uint32_t en0 = (c | ks) ? 1u : 0u;
                mma_ss_bf16(tmem,       adh + off, bdh0 + off, MMA_IDESC, en0);
                mma_ss_bf16(tmem,       adh + off, bdl0 + off, MMA_IDESC, 1u);
                mma_ss_bf16(tmem,       adl + off, bdh0 + off, MMA_IDESC, 1u);
                mma_ss_bf16(tmem + 128, adh + off, bdh1 + off, MMA_IDESC, en0);
                mma_ss_bf16(tmem + 128, adh + off, bdl1 + off, MMA_IDESC, 1u);
                mma_ss_bf16(tmem + 128, adl + off, bdh1 + off, MMA_IDESC, 1u);
            }
            tc_commit(buf ? emp1 : emp0);
        }

        // Final drains: thread 0's parities are correct (7 waits done per
        // barrier, 8 commits issued) — wait the 8th completion of each.
        mbar_wait(emp0, eph0);
        mbar_wait(emp1, eph1);
    }

    // Release the CTA only after thread 0 observed all MMA completions.
    __syncthreads();
    tc_fence_after();

    int row = m0 + wid * 32 + lane;
    float* crow = C + (size_t)row * N + n0;
#pragma unroll 1
    for (int g = 0; g < 8; g++) {
        uint32_t r[32];
        ldtm_x32(r, tmem + g * 32);
        tc_wait_ld();
        const float* bp = bias + n0 + g * 32;
        float* cp = crow + g * 32;
#pragma unroll
        for (int j = 0; j < 32; j += 4) {
            float4 v;
            v.x = __uint_as_float(r[j + 0]) + __ldg(bp + j + 0);
            v.y = __uint_as_float(r[j + 1]) + __ldg(bp + j + 1);
            v.z = __uint_as_float(r[j + 2]) + __ldg(bp + j + 2);
            v.w = __uint_as_float(r[j + 3]) + __ldg(bp + j + 3);
            *(float4*)(cp + j) = v;
        }
    }
    tc_fence_before();
    __syncthreads();
    if (wid == 0) tc_dealloc(tmem, 256);
#endif // TC_PATH
}

// ---------------------------------------------------------------------------
// 2c) Fallback GEMM (NT) via mma.sync m16n8k8 tf32 (plain sm_103 cubin).
// ---------------------------------------------------------------------------
#define LDK 36
#define TF_SMEM (4 * 128 * LDK * 4)

#if defined(__CUDA_ARCH__) && !TC_PATH
__device__ __forceinline__ float tf32r(float x) {
    uint32_t u;
    asm("cvt.rna.tf32.f32 %0, %1;" : "=r"(u) : "f"(x));
    return __uint_as_float(u);
}
#define MMA_TF32(d, a, b)                                                     \
    asm volatile("mma.sync.aligned.m16n8k8.row.col.f32.tf32.tf32.f32 "        \
                 "{%0,%1,%2,%3}, {%4,%5,%6,%7}, {%8,%9}, {%0,%1,%2,%3};"      \
                 : "+f"(d[0]), "+f"(d[1]), "+f"(d[2]), "+f"(d[3])             \
                 : "r"(a[0]), "r"(a[1]), "r"(a[2]), "r"(a[3]),                \
                   "r"(b[0]), "r"(b[1]))
#endif

__global__ __launch_bounds__(256)
void gemm_tf32(const float* __restrict__ A, const float* __restrict__ B,
               const float* __restrict__ bias, float* __restrict__ C, int N)
{
#if defined(__CUDA_ARCH__) && !TC_PATH
    extern __shared__ float sf[];
    float* AsBase = sf;
    float* BsBase = sf + 2 * 128 * LDK;

    int tid  = threadIdx.x;
    int wid  = tid >> 5, lane = tid & 31;
    int g    = lane >> 2, l = lane & 3;
    int wm   = wid >> 2, wn = wid & 3;
    int m0   = blockIdx.y << 7;
    int n0   = blockIdx.x << 7;

    int frow = tid >> 3;
    int fcol = (tid & 7) << 2;

    const float* Ag = A + (size_t)(m0 + frow) * 1024 + fcol;
    const float* Bg = B + (size_t)(n0 + frow) * 1024 + fcol;

    float acc[4][4][4];
#pragma unroll
    for (int i = 0; i < 4; i++)
#pragma unroll
        for (int j = 0; j < 4; j++)
#pragma unroll
            for (int q = 0; q < 4; q++) acc[i][j][q] = 0.0f;

    float4 ra[4], rb[4];
#pragma unroll
    for (int p = 0; p < 4; p++) {
        ra[p] = *(const float4*)(Ag + (size_t)p * 32 * 1024);
        rb[p] = *(const float4*)(Bg + (size_t)p * 32 * 1024);
    }

    for (int c = 0; c < 32; c++) {
        int buf = c & 1;
        float* Ab = AsBase + buf * (128 * LDK);
        float* Bb = BsBase + buf * (128 * LDK);

#pragma unroll
        for (int p = 0; p < 4; p++) {
            int r = p * 32 + frow;
            float4 va = ra[p], vb = rb[p];
            *(float4*)&Ab[r * LDK + fcol] =
                make_float4(tf32r(va.x), tf32r(va.y), tf32r(va.z), tf32r(va.w));
            *(float4*)&Bb[r * LDK + fcol] =
                make_float4(tf32r(vb.x), tf32r(vb.y), tf32r(vb.z), tf32r(vb.w));
        }
        __syncthreads();

        if (c < 31) {
            size_t k0 = (size_t)(c + 1) * 32;
#pragma unroll
            for (int p = 0; p < 4; p++) {
                ra[p] = *(const float4*)(Ag + (size_t)p * 32 * 1024 + k0);
                rb[p] = *(const float4*)(Bg + (size_t)p * 32 * 1024 + k0);
            }
        }

        const float* Aw = Ab + (wm * 64 + g) * LDK;
        const float* Bw = Bb + (wn * 32 + g) * LDK;
#pragma unroll
        for (int ks = 0; ks < 4; ks++) {
            int k = ks * 8 + l;
            uint32_t a[4][4], b[4][2];
#pragma unroll
            for (int mf = 0; mf < 4; mf++) {
                const float* p0 = Aw + mf * 16 * LDK + k;
                a[mf][0] = __float_as_uint(p0[0]);
                a[mf][1] = __float_as_uint(p0[8 * LDK]);
                a[mf][2] = __float_as_uint(p0[4]);
                a[mf][3] = __float_as_uint(p0[8 * LDK + 4]);
            }
#pragma unroll
            for (int nf = 0; nf < 4; nf++) {
                const float* p0 = Bw + nf * 8 * LDK + k;
                b[nf][0] = __float_as_uint(p0[0]);
                b[nf][1] = __float_as_uint(p0[4]);
            }
#pragma unroll
            for (int mf = 0; mf < 4; mf++)
#pragma unroll
                for (int nf = 0; nf < 4; nf++)
                    MMA_TF32(acc[mf][nf], a[mf], b[nf]);
        }
        __syncthreads();
    }

#pragma unroll
    for (int mf = 0; mf < 4; mf++) {
        int r0 = m0 + wm * 64 + mf * 16 + g;
#pragma unroll
        for (int nf = 0; nf < 4; nf++) {
            int cc = n0 + wn * 32 + nf * 8 + 2 * l;
            float b0 = bias[cc], b1 = bias[cc + 1];
            float2 v0 = make_float2(acc[mf][nf][0] + b0, acc[mf][nf][1] + b1);
            float2 v1 = make_float2(acc[mf][nf][2] + b0, acc[mf][nf][3] + b1);
            *(float2*)(C + (size_t)r0 * N + cc)       = v0;
            *(float2*)(C + (size_t)(r0 + 8) * N + cc) = v1;
        }
    }
#endif
}

// ---------------------------------------------------------------------------
// 3) Causal attention (reference quirks preserved). TC-path uses packed
//    fma.rn.f32x2; exp via fast_exp (FMA pipe, no MUFU).
// ---------------------------------------------------------------------------
__global__ __launch_bounds__(128)
void attn_kernel()
{
    __shared__ float Ks[32][64];
    __shared__ float Vs[32][64];

    int bh = blockIdx.x;
    int b  = bh / HH;
    int h  = bh % HH;
    int qt = blockIdx.y;
    int tid = threadIdx.x;
    int t   = qt * 128 + tid;

    const float* qp = g_Q + (size_t)(b * TT + t) * EE + h * DD;
    const float* Kbase = g_Kb + (size_t)(b * TT) * EE + h * DD;
    const float* Vbase = g_Vb + (size_t)(b * TT) * EE + h * DD;
    int smax = qt * 128 + 127;

#if TC_PATH
    ull q2[32];
#pragma unroll
    for (int i = 0; i < 32; i++) q2[i] = ((const ull*)qp)[i];

    ull o2[32];
#pragma unroll
    for (int i = 0; i < 32; i++) o2[i] = 0ULL;

    float mrun = -INFINITY;
    float lrun = 0.0f;

    for (int s0 = 0; s0 <= smax; s0 += 32) {
#pragma unroll
        for (int i = 0; i < 4; i++) {
            int f = tid + i * 128;
            int r = f >> 4;
            int c = (f & 15) << 2;
            ((float4*)Ks)[f] = *(const float4*)(Kbase + (size_t)(s0 + r) * EE + c);
            ((float4*)Vs)[f] = *(const float4*)(Vbase + (size_t)(s0 + r) * EE + c);
        }
        __syncthreads();

        float p[32];
        float tmax = -INFINITY;
#pragma unroll
        for (int j = 0; j < 32; j++) {
            const ulonglong2* kr = (const ulonglong2*)Ks[j];
            ull sa = 0ULL, sb = 0ULL;
#pragma unroll
            for (int d = 0; d < 16; d++) {
                ulonglong2 kv = kr[d];
                fma2(sa, q2[2 * d],     kv.x);
                fma2(sb, q2[2 * d + 1], kv.y);
            }
            float ax, ay, bx, by;
            unpack2(ax, ay, sa);
            unpack2(bx, by, sb);
            float dot = (ax + ay) + (bx + by);
            bool valid = (s0 + j <= t) && (dot != 0.0f);
            p[j] = valid ? dot : -INFINITY;
            tmax = fmaxf(tmax, p[j]);
        }

        float newm = fmaxf(mrun, tmax);
        if (newm != -INFINITY) {
            float factor = (mrun == -INFINITY) ? 0.0f : fast_exp(mrun - newm);
            lrun *= factor;
            ull f2 = pack2(factor, factor);
#pragma unroll
            for (int i = 0; i < 32; i++) o2[i] = mul2(o2[i], f2);
#pragma unroll
            for (int j = 0; j < 32; j++) {
                float e = fast_exp(p[j] - newm);
                lrun += e;
                ull e2 = pack2(e, e);
                const ulonglong2* vr = (const ulonglong2*)Vs[j];
#pragma unroll
                for (int d = 0; d < 16; d++) {
                    ulonglong2 vv = vr[d];
                    fma2(o2[2 * d],     e2, vv.x);
                    fma2(o2[2 * d + 1], e2, vv.y);
                }
            }
            mrun = newm;
        }
        __syncthreads();
    }

    float inv = 1.0f / (lrun * 8.0f);   // normalize + post-softmax 1/sqrt(D)
    ull inv2 = pack2(inv, inv);
    ull* op = (ull*)(g_O + (size_t)(b * TT + t) * EE + h * DD);
#pragma unroll
    for (int i = 0; i < 32; i++) op[i] = mul2(o2[i], inv2);

#else  // scalar fallback
    float4 q4[16];
#pragma unroll
    for (int i = 0; i < 16; i++) q4[i] = *(const float4*)(qp + i * 4);
    float4 o4[16];
#pragma unroll
    for (int i = 0; i < 16; i++) o4[i] = make_float4(0.f, 0.f, 0.f, 0.f);
    float mrun = -INFINITY;
    float lrun = 0.0f;

    for (int s0 = 0; s0 <= smax; s0 += 32) {
#pragma unroll
        for (int i = 0; i < 4; i++) {
            int f = tid + i * 128;
            int r = f >> 4;
            int c = (f & 15) << 2;
            ((float4*)Ks)[f] = *(const float4*)(Kbase + (size_t)(s0 + r) * EE + c);
            ((float4*)Vs)[f] = *(const float4*)(Vbase + (size_t)(s0 + r) * EE + c);
        }
        __syncthreads();

        float p[32];
        float tmax = -INFINITY;
#pragma unroll
        for (int j = 0; j < 32; j++) {
            const float4* kr = (const float4*)Ks[j];
            float4 s4 = make_float4(0.f, 0.f, 0.f, 0.f);
#pragma unroll
            for (int d = 0; d < 16; d++) {
                float4 kv = kr[d];
                s4.x += q4[d].x * kv.x;
                s4.y += q4[d].y * kv.y;
                s4.z += q4[d].z * kv.z;
                s4.w += q4[d].w * kv.w;
            }
            float dot = (s4.x + s4.y) + (s4.z + s4.w);
            bool valid = (s0 + j <= t) && (dot != 0.0f);
            p[j] = valid ? dot : -INFINITY;
            tmax = fmaxf(tmax, p[j]);
        }

        float newm = fmaxf(mrun, tmax);
        if (newm != -INFINITY) {
            float factor = (mrun == -INFINITY) ? 0.0f : fast_exp(mrun - newm);
            lrun *= factor;
#pragma unroll
            for (int i = 0; i < 16; i++) {
                o4[i].x *= factor; o4[i].y *= factor;
                o4[i].z *= factor; o4[i].w *= factor;
            }
#pragma unroll
            for (int j = 0; j < 32; j++) {
                float e = fast_exp(p[j] - newm);
                lrun += e;
                const float4* vr = (const float4*)Vs[j];
#pragma unroll
                for (int d = 0; d < 16; d++) {
                    float4 vv = vr[d];
                    o4[d].x += e * vv.x;
                    o4[d].y += e * vv.y;
                    o4[d].z += e * vv.z;
                    o4[d].w += e * vv.w;
                }
            }
            mrun = newm;
        }
        __syncthreads();
    }

    float inv = 1.0f / (lrun * 8.0f);
    float* op = g_O + (size_t)(b * TT + t) * EE + h * DD;
#pragma unroll
    for (int i = 0; i < 16; i++) {
        float4 o = o4[i];
        *(float4*)(op + i * 4) =
            make_float4(o.x * inv, o.y * inv, o.z * inv, o.w * inv);
    }
#endif
}

// ---------------------------------------------------------------------------
// 4) Loss: single-pass online logsumexp per row (fast_exp — FMA pipe),
//    then mean.
// ---------------------------------------------------------------------------
__global__ __launch_bounds__(256)
void row_loss_kernel(const float* __restrict__ logits,
                     const int* __restrict__ targets)
{
    __shared__ float red_m[256];
    __shared__ float red_s[256];
    int m = blockIdx.x;
    int tid = threadIdx.x;
    const float4* row = (const float4*)(logits + (size_t)m * VV);

    float lm = -INFINITY, ls = 0.0f;
    for (int f = tid; f < VV / 4; f += 256) {
        float4 v = row[f];
        float e0 = v.x, e1 = v.y, e2 = v.z, e3 = v.w;
        float vmax = fmaxf(fmaxf(e0, e1), fmaxf(e2, e3));
        if (vmax > lm) {
            ls = ls * fast_exp(lm - vmax);
            lm = vmax;
        }
        ls += fast_exp(e0 - lm) + fast_exp(e1 - lm) +
              fast_exp(e2 - lm) + fast_exp(e3 - lm);
    }
    red_m[tid] = lm;
    red_s[tid] = ls;
    __syncthreads();
    for (int s = 128; s > 0; s >>= 1) {
        if (tid < s) {
            float m1 = red_m[tid], m2 = red_m[tid + s];
            float s1 = red_s[tid], s2 = red_s[tid + s];
            float mm = fmaxf(m1, m2);
            float ss = (mm == -INFINITY) ? 0.0f
                     : s1 * fast_exp(m1 - mm) + s2 * fast_exp(m2 - mm);
            red_m[tid] = mm;
            red_s[tid] = ss;
        }
        __syncthreads();
    }
    if (tid == 0) {
        int tgt = targets[m];
        float lv = logits[(size_t)m * VV + tgt];
        g_rowloss[m] = -(lv - red_m[0] - logf(red_s[0]));
    }
}

__global__ void final_loss_kernel(float* __restrict__ out)
{
    __shared__ float red[256];
    int tid = threadIdx.x;
    float s = 0.0f;
    for (int i = tid; i < BT; i += 256) s += g_rowloss[i];
    red[tid] = s;
    __syncthreads();
    for (int k = 128; k > 0; k >>= 1) {
        if (tid < k) red[tid] += red[tid + k];
        __syncthreads();
    }
    if (tid == 0) out[(size_t)BT * VV] = red[0] / (float)BT;
}

// ---------------------------------------------------------------------------
// kernel_launch: both GEMM paths launched; exactly one is non-empty in the
// loaded cubin.
// ---------------------------------------------------------------------------
extern "C" void kernel_launch(void* const* d_in, const int* in_sizes, int n_in,
                              void* d_out, int out_size)
{
    const int*   tokens    = (const int*)  d_in[0];
    const int*   targets   = (const int*)  d_in[1];
    const float* tok_table = (const float*)d_in[2];
    const float* pos_emb   = (const float*)d_in[3];
    const float* Wq        = (const float*)d_in[4];
    const float* bq        = (const float*)d_in[5];
    const float* Wk        = (const float*)d_in[6];
    const float* bk        = (const float*)d_in[7];
    const float* Wv        = (const float*)d_in[8];
    const float* bv        = (const float*)d_in[9];
    const float* Wo        = (const float*)d_in[10];
    const float* bo        = (const float*)d_in[11];
    float* out = (float*)d_out;

    cudaFuncSetAttribute(gemm_tc,   cudaFuncAttributeMaxDynamicSharedMemorySize, GEMM_SMEM);
    cudaFuncSetAttribute(gemm_tf32, cudaFuncAttributeMaxDynamicSharedMemorySize, TF_SMEM);

    float *X, *Q, *K, *V, *O;
    cudaGetSymbolAddress((void**)&X, g_X);
    cudaGetSymbolAddress((void**)&Q, g_Q);
    cudaGetSymbolAddress((void**)&K, g_Kb);
    cudaGetSymbolAddress((void**)&V, g_Vb);
    cudaGetSymbolAddress((void**)&O, g_O);

    __nv_bfloat16 *Xh, *Xl, *Oh, *Ol, *Wqh, *Wql, *Wkh, *Wkl, *Wvh, *Wvl, *Woh, *Wol;
    cudaGetSymbolAddress((void**)&Xh, g_Xh);   cudaGetSymbolAddress((void**)&Xl, g_Xl);
    cudaGetSymbolAddress((void**)&Oh, g_Oh);   cudaGetSymbolAddress((void**)&Ol, g_Ol);
    cudaGetSymbolAddress((void**)&Wqh, g_Wqh); cudaGetSymbolAddress((void**)&Wql, g_Wql);
    cudaGetSymbolAddress((void**)&Wkh, g_Wkh); cudaGetSymbolAddress((void**)&Wkl, g_Wkl);
    cudaGetSymbolAddress((void**)&Wvh, g_Wvh); cudaGetSymbolAddress((void**)&Wvl, g_Wvl);
    cudaGetSymbolAddress((void**)&Woh, g_Woh); cudaGetSymbolAddress((void**)&Wol, g_Wol);

    // 1) embed
    embed_kernel<<<BT, 256>>>(tokens, tok_table, pos_emb);

    // 2) tcgen05-path operand prep (no-op in fallback cubin)
    split_tiles_kernel<<<BT, 256>>>(X,  Xh,  Xl);
    split_tiles_kernel<<<EE, 256>>>(Wq, Wqh, Wql);
    split_tiles_kernel<<<EE, 256>>>(Wk, Wkh, Wkl);
    split_tiles_kernel<<<EE, 256>>>(Wv, Wvh, Wvl);
    split_tiles_kernel<<<VV, 256>>>(Wo, Woh, Wol);

    // 3) QKV projections — both paths (one is empty)
    gemm_tc<<<dim3(BT / 128, EE / 256), 128, GEMM_SMEM>>>(Xh, Xl, Wqh, Wql, bq, Q, EE);
    gemm_tc<<<dim3(BT / 128, EE / 256), 128, GEMM_SMEM>>>(Xh, Xl, Wkh, Wkl, bk, K, EE);
    gemm_tc<<<dim3(BT / 128, EE / 256), 128, GEMM_SMEM>>>(Xh, Xl, Wvh, Wvl, bv, V, EE);
    gemm_tf32<<<dim3(EE / 128, BT / 128), 256, TF_SMEM>>>(X, Wq, bq, Q, EE);
    gemm_tf32<<<dim3(EE / 128, BT / 128), 256, TF_SMEM>>>(X, Wk, bk, K, EE);
    gemm_tf32<<<dim3(EE / 128, BT / 128), 256, TF_SMEM>>>(X, Wv, bv, V, EE);

    // 4) attention
    attn_kernel<<<dim3(BB * HH, TT / 128), 128>>>();

    // 5) logits — both paths (one is empty)
    split_tiles_kernel<<<BT, 256>>>(O, Oh, Ol);
    gemm_tc<<<dim3(BT / 128, VV / 256), 128, GEMM_SMEM>>>(Oh, Ol, Woh, Wol, bo, out, VV);
    gemm_tf32<<<dim3(VV / 128, BT / 128), 256, TF_SMEM>>>(O, Wo, bo, out, VV);

    // 6) loss
    row_loss_kernel<<<BT, 256>>>(out, targets);
    final_loss_kernel<<<1, 256>>>(out);
}

// round 17
// speedup vs baseline: 1.5470x; 1.5470x over previous
#include <cuda_runtime.h>
#include <cuda_bf16.h>
#include <math.h>
#include <stdint.h>

// Problem dims
#define BB 2
#define TT 2048
#define BT 4096          // B*T
#define EE 1024
#define HH 16
#define DD 64
#define VV 32000
#define KT 16            // K-chunks of 64 over K=1024 (tcgen05 path)

// Arch-path selection: TC_PATH=1 only in arch-/family-specific device passes
// (tcgen05 + f32x2 legal). Plain compute_103/sm_103 passes compile fallbacks.
#if defined(__CUDA_ARCH__) && (defined(__CUDA_ARCH_FEAT_SM103_ALL) || \
    defined(__CUDA_ARCH_SPECIFIC__) || defined(__CUDA_ARCH_FAMILY_SPECIFIC__))
#define TC_PATH 1
#else
#define TC_PATH 0
#endif

// ---------------------------------------------------------------------------
// Scratch (static device globals)
// ---------------------------------------------------------------------------
__device__ float g_X[BT * EE];      // fallback cubin only
__device__ float g_Q[BT * EE];
__device__ float g_Kb[BT * EE];
__device__ float g_Vb[BT * EE];
__device__ float g_O[BT * EE];      // fallback cubin only
__device__ float g_rowloss[BT];

// bf16 hi/lo operands as pre-swizzled SW128 tiles (128 rows x 64 cols = 16KB)
__device__ __nv_bfloat16 g_Xh[BT * EE],  g_Xl[BT * EE];
__device__ __nv_bfloat16 g_Oh[BT * EE],  g_Ol[BT * EE];
__device__ __nv_bfloat16 g_Wqh[EE * EE], g_Wql[EE * EE];
__device__ __nv_bfloat16 g_Wkh[EE * EE], g_Wkl[EE * EE];
__device__ __nv_bfloat16 g_Wvh[EE * EE], g_Wvl[EE * EE];
__device__ __nv_bfloat16 g_Woh[(size_t)VV * EE], g_Wol[(size_t)VV * EE];

// Split 8 consecutive f32 into bf16 hi/lo packed uint4s.
__device__ __forceinline__ void split8(const float* v, uint4& hp, uint4& lp) {
    uint32_t hw[4], lw[4];
#pragma unroll
    for (int i = 0; i < 4; i++) {
        __nv_bfloat16 h0 = __float2bfloat16(v[2 * i]);
        __nv_bfloat16 h1 = __float2bfloat16(v[2 * i + 1]);
        __nv_bfloat16 l0 = __float2bfloat16(v[2 * i]     - __bfloat162float(h0));
        __nv_bfloat16 l1 = __float2bfloat16(v[2 * i + 1] - __bfloat162float(h1));
        hw[i] = (uint32_t)__bfloat16_as_ushort(h0) |
                ((uint32_t)__bfloat16_as_ushort(h1) << 16);
        lw[i] = (uint32_t)__bfloat16_as_ushort(l0) |
                ((uint32_t)__bfloat16_as_ushort(l1) << 16);
    }
    hp = make_uint4(hw[0], hw[1], hw[2], hw[3]);
    lp = make_uint4(lw[0], lw[1], lw[2], lw[3]);
}

// ---------------------------------------------------------------------------
// tcgen05 / bulk-async helpers (arch-specific pass only)
// ---------------------------------------------------------------------------
#if TC_PATH
__device__ __forceinline__ uint32_t smem_u32(const void* p) {
    uint32_t a;
    asm("{ .reg .u64 t; cvta.to.shared.u64 t, %1; cvt.u32.u64 %0, t; }"
        : "=r"(a) : "l"(p));
    return a;
}
__device__ __forceinline__ uint64_t sw128_desc(uint32_t addr) {
    const uint64_t base = (uint64_t(2) << 61) | (uint64_t(1) << 46)
                        | (uint64_t(64) << 32) | (uint64_t(1) << 16);
    return base | ((uint64_t)(addr >> 4) & 0x3FFF);
}
__device__ __forceinline__ void tc_alloc(uint32_t smem_res, uint32_t ncols) {
    asm volatile("tcgen05.alloc.cta_group::1.sync.aligned.shared::cta.b32 [%0], %1;"
                 :: "r"(smem_res), "r"(ncols) : "memory");
}
__device__ __forceinline__ void tc_relinquish() {
    asm volatile("tcgen05.relinquish_alloc_permit.cta_group::1.sync.aligned;");
}
__device__ __forceinline__ void tc_dealloc(uint32_t tmem, uint32_t ncols) {
    asm volatile("tcgen05.dealloc.cta_group::1.sync.aligned.b32 %0, %1;"
                 :: "r"(tmem), "r"(ncols));
}
__device__ __forceinline__ void mbar_init(uint32_t mb, uint32_t cnt) {
    asm volatile("mbarrier.init.shared.b64 [%0], %1;" :: "r"(mb), "r"(cnt) : "memory");
}
__device__ __forceinline__ void mbar_expect_tx(uint32_t mb, uint32_t bytes) {
    asm volatile("mbarrier.arrive.expect_tx.shared.b64 _, [%0], %1;"
                 :: "r"(mb), "r"(bytes) : "memory");
}
__device__ __forceinline__ void tc_commit(uint32_t mb) {
    asm volatile("tcgen05.commit.cta_group::1.mbarrier::arrive::one.shared::cluster.b64 [%0];"
                 :: "r"(mb) : "memory");
}
__device__ __forceinline__ void mbar_wait(uint32_t mb, uint32_t parity) {
    uint32_t done;
    asm volatile("{\n\t.reg .pred p;\n\t"
                 "mbarrier.try_wait.parity.acquire.cta.shared::cta.b64 p, [%1], %2;\n\t"
                 "selp.b32 %0, 1, 0, p;\n\t}"
                 : "=r"(done) : "r"(mb), "r"(parity) : "memory");
    while (!done) {
        asm volatile("{\n\t.reg .pred p;\n\t"
                     "mbarrier.try_wait.parity.acquire.cta.shared::cta.b64 p, [%1], %2, 0x989680;\n\t"
                     "selp.b32 %0, 1, 0, p;\n\t}"
                     : "=r"(done) : "r"(mb), "r"(parity) : "memory");
    }
}
__device__ __forceinline__ void bulk_cp(uint32_t dst, const void* src,
                                        uint32_t bytes, uint32_t mb) {
    asm volatile("cp.async.bulk.shared::cta.global.mbarrier::complete_tx::bytes "
                 "[%0], [%1], %2, [%3];"
                 :: "r"(dst), "l"(src), "r"(bytes), "r"(mb) : "memory");
}
__device__ __forceinline__ void tc_fence_after() {
    asm volatile("tcgen05.fence::after_thread_sync;" ::: "memory");
}
__device__ __forceinline__ void tc_fence_before() {
    asm volatile("tcgen05.fence::before_thread_sync;" ::: "memory");
}
__device__ __forceinline__ void tc_wait_ld() {
    asm volatile("tcgen05.wait::ld.sync.aligned;" ::: "memory");
}
__device__ __forceinline__ void mma_ss_bf16(uint32_t d_tmem, uint64_t a_desc,
                                            uint64_t b_desc, uint32_t idesc,
                                            uint32_t en) {
    asm volatile(
        "{\n\t"
        ".reg .pred p;\n\t"
        "setp.ne.u32 p, %5, 0;\n\t"
        "tcgen05.mma.cta_group::1.kind::f16 [%0], %1, %2, %3, {%4, %4, %4, %4}, p;\n\t"
        "}"
        :: "r"(d_tmem), "l"(a_desc), "l"(b_desc), "r"(idesc), "r"(0u), "r"(en)
        : "memory");
}
__device__ __forceinline__ void ldtm_x32(uint32_t* r, uint32_t tmem_addr) {
    asm volatile(
        "tcgen05.ld.sync.aligned.32x32b.x32.b32 "
        "{%0, %1, %2, %3, %4, %5, %6, %7, "
        " %8, %9, %10, %11, %12, %13, %14, %15, "
        " %16, %17, %18, %19, %20, %21, %22, %23, "
        " %24, %25, %26, %27, %28, %29, %30, %31}, [%32];"
        : "=r"(r[0]),  "=r"(r[1]),  "=r"(r[2]),  "=r"(r[3]),
          "=r"(r[4]),  "=r"(r[5]),  "=r"(r[6]),  "=r"(r[7]),
          "=r"(r[8]),  "=r"(r[9]),  "=r"(r[10]), "=r"(r[11]),
          "=r"(r[12]), "=r"(r[13]), "=r"(r[14]), "=r"(r[15]),
          "=r"(r[16]), "=r"(r[17]), "=r"(r[18]), "=r"(r[19]),
          "=r"(r[20]), "=r"(r[21]), "=r"(r[22]), "=r"(r[23]),
          "=r"(r[24]), "=r"(r[25]), "=r"(r[26]), "=r"(r[27]),
          "=r"(r[28]), "=r"(r[29]), "=r"(r[30]), "=r"(r[31])
        : "r"(tmem_addr));
}
#define MMA_IDESC 0x8200490u   // F32 accum, BF16xBF16, M=128, N=128

// packed f32x2 helpers
typedef unsigned long long ull;
__device__ __forceinline__ void fma2(ull& d, ull a, ull b) {
    asm("fma.rn.f32x2 %0, %1, %2, %3;" : "=l"(d) : "l"(a), "l"(b), "l"(d));
}
__device__ __forceinline__ ull mul2(ull a, ull b) {
    ull d; asm("mul.rn.f32x2 %0, %1, %2;" : "=l"(d) : "l"(a), "l"(b)); return d;
}
__device__ __forceinline__ ull pack2(float lo, float hi) {
    ull r; asm("mov.b64 %0, {%1, %2};" : "=l"(r) : "f"(lo), "f"(hi)); return r;
}
__device__ __forceinline__ void unpack2(float& lo, float& hi, ull v) {
    asm("mov.b64 {%0, %1}, %2;" : "=f"(lo), "=f"(hi) : "l"(v));
}
#endif // TC_PATH

// ---------------------------------------------------------------------------
// 1) Embedding, fused with the hi/lo split in the TC cubin (no g_X round
//    trip). 128 threads, 8 cols/thread. Fallback cubin writes f32 g_X.
// ---------------------------------------------------------------------------
__global__ __launch_bounds__(128)
void embed_kernel(const int* __restrict__ tokens,
                  const float* __restrict__ tok_table,
                  const float* __restrict__ pos_emb)
{
    int m   = blockIdx.x;
    int tid = threadIdx.x;
    int tok = tokens[m];
    int tp  = m % TT;
    const float4* tr = (const float4*)(tok_table + (size_t)tok * EE);
    const float4* pr = (const float4*)(pos_emb  + (size_t)tp  * EE);
    float4 a0 = tr[2 * tid], a1 = tr[2 * tid + 1];
    float4 b0 = pr[2 * tid], b1 = pr[2 * tid + 1];
    float v[8] = {a0.x + b0.x, a0.y + b0.y, a0.z + b0.z, a0.w + b0.w,
                  a1.x + b1.x, a1.y + b1.y, a1.z + b1.z, a1.w + b1.w};
#if TC_PATH
    uint4 hp, lp;
    split8(v, hp, lp);
    int mt = m >> 7, r = m & 127;
    int k  = tid << 3, kc = k >> 6, cc = k & 63;
    size_t tb = ((size_t)mt * KT + kc) * 16384;
    uint32_t boff = (uint32_t)(r * 128 + cc * 2);
    uint32_t sw = boff ^ ((boff >> 3) & 0x70);
    *(uint4*)((char*)g_Xh + tb + sw) = hp;
    *(uint4*)((char*)g_Xl + tb + sw) = lp;
#else
    float4* xr = (float4*)(g_X + (size_t)m * EE);
    xr[2 * tid]     = make_float4(v[0], v[1], v[2], v[3]);
    xr[2 * tid + 1] = make_float4(v[4], v[5], v[6], v[7]);
#endif
}

// ---------------------------------------------------------------------------
// 2a) Split f32 [R,1024] weights into pre-swizzled bf16 hi/lo SW128 tiles.
//     2 rows per 256-thread block; 8 cols/thread -> one 16B swizzle unit ->
//     uint4 stores. grid = R/2. Empty in fallback cubin.
// ---------------------------------------------------------------------------
__global__ __launch_bounds__(256)
void split_tiles_kernel(const float* __restrict__ src,
                        __nv_bfloat16* __restrict__ hi,
                        __nv_bfloat16* __restrict__ lo)
{
#if TC_PATH
    int lr   = threadIdx.x >> 7;
    int ltid = threadIdx.x & 127;
    int row  = blockIdx.x * 2 + lr;
    const float4* sp = (const float4*)(src + (size_t)row * EE);
    float4 a0 = sp[2 * ltid], a1 = sp[2 * ltid + 1];
    float v[8] = {a0.x, a0.y, a0.z, a0.w, a1.x, a1.y, a1.z, a1.w};
    uint4 hp, lp;
    split8(v, hp, lp);
    int mt = row >> 7, r = row & 127;
    int k  = ltid << 3, kc = k >> 6, cc = k & 63;
    size_t tb = ((size_t)mt * KT + kc) * 16384;
    uint32_t boff = (uint32_t)(r * 128 + cc * 2);
    uint32_t sw = boff ^ ((boff >> 3) & 0x70);
    *(uint4*)((char*)hi + tb + sw) = hp;
    *(uint4*)((char*)lo + tb + sw) = lp;
#endif
}

// ---------------------------------------------------------------------------
// 2b) tcgen05 bf16-split GEMM (NT). CTA tile 128x256, K-chunk 64, bulk-async
//     double-buffered pipeline driven by thread 0, SS MMA, 3-product split.
//     grid = (M/128, N/256), 128 threads.  [unchanged from the 2044us run]
// ---------------------------------------------------------------------------
#define GEMM_SMEM 197632   // 1024 header + 2 x 96KB buffers

__global__ __launch_bounds__(128, 1)
void gemm_tc(const __nv_bfloat16* __restrict__ Ah, const __nv_bfloat16* __restrict__ Al,
             const __nv_bfloat16* __restrict__ Bh, const __nv_bfloat16* __restrict__ Bl,
             const float* __restrict__ bias, float* __restrict__ C, int N)
{
#if TC_PATH
    extern __shared__ char sm[];
    uint32_t sb  = smem_u32(sm);
    int tid  = threadIdx.x;
    int wid  = tid >> 5;
    int lane = tid & 31;
    int mt   = blockIdx.x;                // m-tile (fast dim for L2 reuse of A)
    int nt0  = blockIdx.y * 2;
    int m0   = mt * 128;
    int n0   = blockIdx.y * 256;

    uint32_t full0 = sb + 8,  full1 = sb + 16;
    uint32_t emp0  = sb + 24, emp1  = sb + 32;

    if (wid == 0) {
        tc_alloc(sb, 256);
        tc_relinquish();
    }
    if (tid == 0) {
        mbar_init(full0, 1); mbar_init(full1, 1);
        mbar_init(emp0, 1);  mbar_init(emp1, 1);
    }
    __syncthreads();
    uint32_t tmem;
    asm volatile("ld.shared.b32 %0, [%1];" : "=r"(tmem) : "r"(sb));

    if (tid == 0) {
        const char* baAh  = (const char*)Ah + (size_t)mt * KT * 16384;
        const char* baAl  = (const char*)Al + (size_t)mt * KT * 16384;
        const char* baB0h = (const char*)Bh + (size_t)nt0 * KT * 16384;
        const char* baB1h = (const char*)Bh + (size_t)(nt0 + 1) * KT * 16384;
        const char* baB0l = (const char*)Bl + (size_t)nt0 * KT * 16384;
        const char* baB1l = (const char*)Bl + (size_t)(nt0 + 1) * KT * 16384;

        int fph0 = 0, fph1 = 0, eph0 = 0, eph1 = 0;
        for (int c = 0; c < KT; c++) {
            int buf = c & 1;
            uint32_t bb = sb + 1024 + buf * 98304;
            uint32_t full = buf ? full1 : full0;

            if (c >= 2) {                 // buffer free when its prior MMAs done
                if (buf) { mbar_wait(emp1, eph1); eph1 ^= 1; }
                else     { mbar_wait(emp0, eph0); eph0 ^= 1; }
            }

            size_t co = (size_t)c * 16384;
            mbar_expect_tx(full, 98304);
            bulk_cp(bb,         baAh  + co, 16384, full);
            bulk_cp(bb + 16384, baAl  + co, 16384, full);
            bulk_cp(bb + 32768, baB0h + co, 16384, full);
            bulk_cp(bb + 49152, baB1h + co, 16384, full);
            bulk_cp(bb + 65536, baB0l + co, 16384, full);
            bulk_cp(bb + 81920, baB1l + co, 16384, full);

            if (buf) { mbar_wait(full1, fph1); fph1 ^= 1; }
            else     { mbar_wait(full0, fph0); fph0 ^= 1; }

            uint64_t adh  = sw128_desc(bb);
            uint64_t adl  = sw128_desc(bb + 16384);
            uint64_t bdh0 = sw128_desc(bb + 32768);
            uint64_t bdh1 = sw128_desc(bb + 49152);
            uint64_t bdl0 = sw128_desc(bb + 65536);
            uint64_t bdl1 = sw128_desc(bb + 81920);
#pragma unroll
            for (int ks = 0; ks < 4; ks++) {
                uint32_t off = ks * 2;              // 16 bf16 = 32B = 2 units
                uint32_t en0 = (c | ks) ? 1u : 0u;
                mma_ss_bf16(tmem,       adh + off, bdh0 + off, MMA_IDESC, en0);
                mma_ss_bf16(tmem,       adh + off, bdl0 + off, MMA_IDESC, 1u);
                mma_ss_bf16(tmem,       adl + off, bdh0 + off, MMA_IDESC, 1u);
                mma_ss_bf16(tmem + 128, adh + off, bdh1 + off, MMA_IDESC, en0);
                mma_ss_bf16(tmem + 128, adh + off, bdl1 + off, MMA_IDESC, 1u);
                mma_ss_bf16(tmem + 128, adl + off, bdh1 + off, MMA_IDESC, 1u);
            }
            tc_commit(buf ? emp1 : emp0);
        }

        // Final drains: thread 0's parities are correct (7 waits done per
        // barrier, 8 commits issued) — wait the 8th completion of each.
        mbar_wait(emp0, eph0);
        mbar_wait(emp1, eph1);
    }

    // Release the CTA only after thread 0 observed all MMA completions.
    __syncthreads();
    tc_fence_after();

    int row = m0 + wid * 32 + lane;
    float* crow = C + (size_t)row * N + n0;
#pragma unroll 1
    for (int g = 0; g < 8; g++) {
        uint32_t r[32];
        ldtm_x32(r, tmem + g * 32);
        tc_wait_ld();
        const float* bp = bias + n0 + g * 32;
        float* cp = crow + g * 32;
#pragma unroll
        for (int j = 0; j < 32; j += 4) {
            float4 v;
            v.x = __uint_as_float(r[j + 0]) + __ldg(bp + j + 0);
            v.y = __uint_as_float(r[j + 1]) + __ldg(bp + j + 1);
            v.z = __uint_as_float(r[j + 2]) + __ldg(bp + j + 2);
            v.w = __uint_as_float(r[j + 3]) + __ldg(bp + j + 3);
            *(float4*)(cp + j) = v;
        }
    }
    tc_fence_before();
    __syncthreads();
    if (wid == 0) tc_dealloc(tmem, 256);
#endif // TC_PATH
}

// ---------------------------------------------------------------------------
// 2c) Fallback GEMM (NT) via mma.sync m16n8k8 tf32 (plain sm_103 cubin).
// ---------------------------------------------------------------------------
#define LDK 36
#define TF_SMEM (4 * 128 * LDK * 4)

#if defined(__CUDA_ARCH__) && !TC_PATH
__device__ __forceinline__ float tf32r(float x) {
    uint32_t u;
    asm("cvt.rna.tf32.f32 %0, %1;" : "=r"(u) : "f"(x));
    return __uint_as_float(u);
}
#define MMA_TF32(d, a, b)                                                     \
    asm volatile("mma.sync.aligned.m16n8k8.row.col.f32.tf32.tf32.f32 "        \
                 "{%0,%1,%2,%3}, {%4,%5,%6,%7}, {%8,%9}, {%0,%1,%2,%3};"      \
                 : "+f"(d[0]), "+f"(d[1]), "+f"(d[2]), "+f"(d[3])             \
                 : "r"(a[0]), "r"(a[1]), "r"(a[2]), "r"(a[3]),                \
                   "r"(b[0]), "r"(b[1]))
#endif

__global__ __launch_bounds__(256)
void gemm_tf32(const float* __restrict__ A, const float* __restrict__ B,
               const float* __restrict__ bias, float* __restrict__ C, int N)
{
#if defined(__CUDA_ARCH__) && !TC_PATH
    extern __shared__ float sf[];
    float* AsBase = sf;
    float* BsBase = sf + 2 * 128 * LDK;

    int tid  = threadIdx.x;
    int wid  = tid >> 5, lane = tid & 31;
    int g    = lane >> 2, l = lane & 3;
    int wm   = wid >> 2, wn = wid & 3;
    int m0   = blockIdx.y << 7;
    int n0   = blockIdx.x << 7;

    int frow = tid >> 3;
    int fcol = (tid & 7) << 2;

    const float* Ag = A + (size_t)(m0 + frow) * 1024 + fcol;
    const float* Bg = B + (size_t)(n0 + frow) * 1024 + fcol;

    float acc[4][4][4];
#pragma unroll
    for (int i = 0; i < 4; i++)
#pragma unroll
        for (int j = 0; j < 4; j++)
#pragma unroll
            for (int q = 0; q < 4; q++) acc[i][j][q] = 0.0f;

    float4 ra[4], rb[4];
#pragma unroll
    for (int p = 0; p < 4; p++) {
        ra[p] = *(const float4*)(Ag + (size_t)p * 32 * 1024);
        rb[p] = *(const float4*)(Bg + (size_t)p * 32 * 1024);
    }

    for (int c = 0; c < 32; c++) {
        int buf = c & 1;
        float* Ab = AsBase + buf * (128 * LDK);
        float* Bb = BsBase + buf * (128 * LDK);

#pragma unroll
        for (int p = 0; p < 4; p++) {
            int r = p * 32 + frow;
            float4 va = ra[p], vb = rb[p];
            *(float4*)&Ab[r * LDK + fcol] =
                make_float4(tf32r(va.x), tf32r(va.y), tf32r(va.z), tf32r(va.w));
            *(float4*)&Bb[r * LDK + fcol] =
                make_float4(tf32r(vb.x), tf32r(vb.y), tf32r(vb.z), tf32r(vb.w));
        }
        __syncthreads();

        if (c < 31) {
            size_t k0 = (size_t)(c + 1) * 32;
#pragma unroll
            for (int p = 0; p < 4; p++) {
                ra[p] = *(const float4*)(Ag + (size_t)p * 32 * 1024 + k0);
                rb[p] = *(const float4*)(Bg + (size_t)p * 32 * 1024 + k0);
            }
        }

        const float* Aw = Ab + (wm * 64 + g) * LDK;
        const float* Bw = Bb + (wn * 32 + g) * LDK;
#pragma unroll
        for (int ks = 0; ks < 4; ks++) {
            int k = ks * 8 + l;
            uint32_t a[4][4], b[4][2];
#pragma unroll
            for (int mf = 0; mf < 4; mf++) {
                const float* p0 = Aw + mf * 16 * LDK + k;
                a[mf][0] = __float_as_uint(p0[0]);
                a[mf][1] = __float_as_uint(p0[8 * LDK]);
                a[mf][2] = __float_as_uint(p0[4]);
                a[mf][3] = __float_as_uint(p0[8 * LDK + 4]);
            }
#pragma unroll
            for (int nf = 0; nf < 4; nf++) {
                const float* p0 = Bw + nf * 8 * LDK + k;
                b[nf][0] = __float_as_uint(p0[0]);
                b[nf][1] = __float_as_uint(p0[4]);
            }
#pragma unroll
            for (int mf = 0; mf < 4; mf++)
#pragma unroll
                for (int nf = 0; nf < 4; nf++)
                    MMA_TF32(acc[mf][nf], a[mf], b[nf]);
        }
        __syncthreads();
    }

#pragma unroll
    for (int mf = 0; mf < 4; mf++) {
        int r0 = m0 + wm * 64 + mf * 16 + g;
#pragma unroll
        for (int nf = 0; nf < 4; nf++) {
            int cc = n0 + wn * 32 + nf * 8 + 2 * l;
            float b0 = bias[cc], b1 = bias[cc + 1];
            float2 v0 = make_float2(acc[mf][nf][0] + b0, acc[mf][nf][1] + b1);
            float2 v1 = make_float2(acc[mf][nf][2] + b0, acc[mf][nf][3] + b1);
            *(float2*)(C + (size_t)r0 * N + cc)       = v0;
            *(float2*)(C + (size_t)(r0 + 8) * N + cc) = v1;
        }
    }
#endif
}

// ---------------------------------------------------------------------------
// 3) Causal attention (reference quirks preserved). TC-path: f32x2 math,
//    __expf (MUFU pipe, overlaps FMA), epilogue writes Oh/Ol tiles directly.
// ---------------------------------------------------------------------------
__global__ __launch_bounds__(128)
void attn_kernel()
{
    __shared__ float Ks[32][64];
    __shared__ float Vs[32][64];

    int bh = blockIdx.x;
    int b  = bh / HH;
    int h  = bh % HH;
    int qt = blockIdx.y;
    int tid = threadIdx.x;
    int t   = qt * 128 + tid;

    const float* qp = g_Q + (size_t)(b * TT + t) * EE + h * DD;
    const float* Kbase = g_Kb + (size_t)(b * TT) * EE + h * DD;
    const float* Vbase = g_Vb + (size_t)(b * TT) * EE + h * DD;
    int smax = qt * 128 + 127;

#if TC_PATH
    ull q2[32];
#pragma unroll
    for (int i = 0; i < 32; i++) q2[i] = ((const ull*)qp)[i];

    ull o2[32];
#pragma unroll
    for (int i = 0; i < 32; i++) o2[i] = 0ULL;

    float mrun = -INFINITY;
    float lrun = 0.0f;

    for (int s0 = 0; s0 <= smax; s0 += 32) {
#pragma unroll
        for (int i = 0; i < 4; i++) {
            int f = tid + i * 128;
            int r = f >> 4;
            int c = (f & 15) << 2;
            ((float4*)Ks)[f] = *(const float4*)(Kbase + (size_t)(s0 + r) * EE + c);
            ((float4*)Vs)[f] = *(const float4*)(Vbase + (size_t)(s0 + r) * EE + c);
        }
        __syncthreads();

        float p[32];
        float tmax = -INFINITY;
#pragma unroll
        for (int j = 0; j < 32; j++) {
            const ulonglong2* kr = (const ulonglong2*)Ks[j];
            ull sa = 0ULL, sb = 0ULL;
#pragma unroll
            for (int d = 0; d < 16; d++) {
                ulonglong2 kv = kr[d];
                fma2(sa, q2[2 * d],     kv.x);
                fma2(sb, q2[2 * d + 1], kv.y);
            }
            float ax, ay, bx, by;
            unpack2(ax, ay, sa);
            unpack2(bx, by, sb);
            float dot = (ax + ay) + (bx + by);
            bool valid = (s0 + j <= t) && (dot != 0.0f);
            p[j] = valid ? dot : -INFINITY;
            tmax = fmaxf(tmax, p[j]);
        }

        float newm = fmaxf(mrun, tmax);
        if (newm != -INFINITY) {
            float factor = (mrun == -INFINITY) ? 0.0f : __expf(mrun - newm);
            lrun *= factor;
            ull f2 = pack2(factor, factor);
#pragma unroll
            for (int i = 0; i < 32; i++) o2[i] = mul2(o2[i], f2);
#pragma unroll
            for (int j = 0; j < 32; j++) {
                float e = __expf(p[j] - newm);
                lrun += e;
                ull e2 = pack2(e, e);
                const ulonglong2* vr = (const ulonglong2*)Vs[j];
#pragma unroll
                for (int d = 0; d < 16; d++) {
                    ulonglong2 vv = vr[d];
                    fma2(o2[2 * d],     e2, vv.x);
                    fma2(o2[2 * d + 1], e2, vv.y);
                }
            }
            mrun = newm;
        }
        __syncthreads();
    }

    // normalize + post-softmax 1/sqrt(D); emit bf16 hi/lo tiles directly.
    // Head h's 64 cols == k-chunk h of the [BT, E] tile grid exactly.
    float inv = 1.0f / (lrun * 8.0f);
    int mrow = b * TT + t;
    int mt = mrow >> 7, r = mrow & 127;
    size_t tb = ((size_t)mt * KT + h) * 16384;
    uint32_t rb = (uint32_t)(r * 128);
#pragma unroll
    for (int u = 0; u < 8; u++) {
        float v[8];
#pragma unroll
        for (int j = 0; j < 4; j++) {
            float vlo, vhi;
            unpack2(vlo, vhi, o2[4 * u + j]);
            v[2 * j]     = vlo * inv;
            v[2 * j + 1] = vhi * inv;
        }
        uint4 hp, lp;
        split8(v, hp, lp);
        uint32_t boff = rb + u * 16;
        uint32_t sw = boff ^ ((boff >> 3) & 0x70);
        *(uint4*)((char*)g_Oh + tb + sw) = hp;
        *(uint4*)((char*)g_Ol + tb + sw) = lp;
    }

#else  // scalar fallback
    float4 q4[16];
#pragma unroll
    for (int i = 0; i < 16; i++) q4[i] = *(const float4*)(qp + i * 4);
    float4 o4[16];
#pragma unroll
    for (int i = 0; i < 16; i++) o4[i] = make_float4(0.f, 0.f, 0.f, 0.f);
    float mrun = -INFINITY;
    float lrun = 0.0f;

    for (int s0 = 0; s0 <= smax; s0 += 32) {
#pragma unroll
        for (int i = 0; i < 4; i++) {
            int f = tid + i * 128;
            int r = f >> 4;
            int c = (f & 15) << 2;
            ((float4*)Ks)[f] = *(const float4*)(Kbase + (size_t)(s0 + r) * EE + c);
            ((float4*)Vs)[f] = *(const float4*)(Vbase + (size_t)(s0 + r) * EE + c);
        }
        __syncthreads();

        float p[32];
        float tmax = -INFINITY;
#pragma unroll
        for (int j = 0; j < 32; j++) {
            const float4* kr = (const float4*)Ks[j];
            float4 s4 = make_float4(0.f, 0.f, 0.f, 0.f);
#pragma unroll
            for (int d = 0; d < 16; d++) {
                float4 kv = kr[d];
                s4.x += q4[d].x * kv.x;
                s4.y += q4[d].y * kv.y;
                s4.z += q4[d].z * kv.z;
                s4.w += q4[d].w * kv.w;
            }
            float dot = (s4.x + s4.y) + (s4.z + s4.w);
            bool valid = (s0 + j <= t) && (dot != 0.0f);
            p[j] = valid ? dot : -INFINITY;
            tmax = fmaxf(tmax, p[j]);
        }

        float newm = fmaxf(mrun, tmax);
        if (newm != -INFINITY) {
            float factor = (mrun == -INFINITY) ? 0.0f : __expf(mrun - newm);
            lrun *= factor;
#pragma unroll
            for (int i = 0; i < 16; i++) {
                o4[i].x *= factor; o4[i].y *= factor;
                o4[i].z *= factor; o4[i].w *= factor;
            }
#pragma unroll
            for (int j = 0; j < 32; j++) {
                float e = __expf(p[j] - newm);
                lrun += e;
                const float4* vr = (const float4*)Vs[j];
#pragma unroll
                for (int d = 0; d < 16; d++) {
                    float4 vv = vr[d];
                    o4[d].x += e * vv.x;
                    o4[d].y += e * vv.y;
                    o4[d].z += e * vv.z;
                    o4[d].w += e * vv.w;
                }
            }
            mrun = newm;
        }
        __syncthreads();
    }

    float inv = 1.0f / (lrun * 8.0f);
    float* op = g_O + (size_t)(b * TT + t) * EE + h * DD;
#pragma unroll
    for (int i = 0; i < 16; i++) {
        float4 o = o4[i];
        *(float4*)(op + i * 4) =
            make_float4(o.x * inv, o.y * inv, o.z * inv, o.w * inv);
    }
#endif
}

// ---------------------------------------------------------------------------
// 4) Loss: single-pass online logsumexp per row (__expf — MUFU overlaps the
//    LDG stream), then mean.
// ---------------------------------------------------------------------------
__global__ __launch_bounds__(256)
void row_loss_kernel(const float* __restrict__ logits,
                     const int* __restrict__ targets)
{
    __shared__ float red_m[256];
    __shared__ float red_s[256];
    int m = blockIdx.x;
    int tid = threadIdx.x;
    const float4* row = (const float4*)(logits + (size_t)m * VV);

    float lm = -INFINITY, ls = 0.0f;
    for (int f = tid; f < VV / 4; f += 256) {
        float4 v = row[f];
        float e0 = v.x, e1 = v.y, e2 = v.z, e3 = v.w;
        float vmax = fmaxf(fmaxf(e0, e1), fmaxf(e2, e3));
        if (vmax > lm) {
            ls = ls * __expf(lm - vmax);
            lm = vmax;
        }
        ls += __expf(e0 - lm) + __expf(e1 - lm) +
              __expf(e2 - lm) + __expf(e3 - lm);
    }
    red_m[tid] = lm;
    red_s[tid] = ls;
    __syncthreads();
    for (int s = 128; s > 0; s >>= 1) {
        if (tid < s) {
            float m1 = red_m[tid], m2 = red_m[tid + s];
            float s1 = red_s[tid], s2 = red_s[tid + s];
            float mm = fmaxf(m1, m2);
            float ss = (mm == -INFINITY) ? 0.0f
                     : s1 * __expf(m1 - mm) + s2 * __expf(m2 - mm);
            red_m[tid] = mm;
            red_s[tid] = ss;
        }
        __syncthreads();
    }
    if (tid == 0) {
        int tgt = targets[m];
        float lv = logits[(size_t)m * VV + tgt];
        g_rowloss[m] = -(lv - red_m[0] - logf(red_s[0]));
    }
}

__global__ void final_loss_kernel(float* __restrict__ out)
{
    __shared__ float red[256];
    int tid = threadIdx.x;
    float s = 0.0f;
    for (int i = tid; i < BT; i += 256) s += g_rowloss[i];
    red[tid] = s;
    __syncthreads();
    for (int k = 128; k > 0; k >>= 1) {
        if (tid < k) red[tid] += red[tid + k];
        __syncthreads();
    }
    if (tid == 0) out[(size_t)BT * VV] = red[0] / (float)BT;
}

// ---------------------------------------------------------------------------
// kernel_launch: both GEMM paths launched; exactly one is non-empty in the
// loaded cubin.
// ---------------------------------------------------------------------------
extern "C" void kernel_launch(void* const* d_in, const int* in_sizes, int n_in,
                              void* d_out, int out_size)
{
    const int*   tokens    = (const int*)  d_in[0];
    const int*   targets   = (const int*)  d_in[1];
    const float* tok_table = (const float*)d_in[2];
    const float* pos_emb   = (const float*)d_in[3];
    const float* Wq        = (const float*)d_in[4];
    const float* bq        = (const float*)d_in[5];
    const float* Wk        = (const float*)d_in[6];
    const float* bk        = (const float*)d_in[7];
    const float* Wv        = (const float*)d_in[8];
    const float* bv        = (const float*)d_in[9];
    const float* Wo        = (const float*)d_in[10];
    const float* bo        = (const float*)d_in[11];
    float* out = (float*)d_out;

    cudaFuncSetAttribute(gemm_tc,   cudaFuncAttributeMaxDynamicSharedMemorySize, GEMM_SMEM);
    cudaFuncSetAttribute(gemm_tf32, cudaFuncAttributeMaxDynamicSharedMemorySize, TF_SMEM);

    float *X, *Q, *K, *V, *O;
    cudaGetSymbolAddress((void**)&X, g_X);
    cudaGetSymbolAddress((void**)&Q, g_Q);
    cudaGetSymbolAddress((void**)&K, g_Kb);
    cudaGetSymbolAddress((void**)&V, g_Vb);
    cudaGetSymbolAddress((void**)&O, g_O);

    __nv_bfloat16 *Xh, *Xl, *Oh, *Ol, *Wqh, *Wql, *Wkh, *Wkl, *Wvh, *Wvl, *Woh, *Wol;
    cudaGetSymbolAddress((void**)&Xh, g_Xh);   cudaGetSymbolAddress((void**)&Xl, g_Xl);
    cudaGetSymbolAddress((void**)&Oh, g_Oh);   cudaGetSymbolAddress((void**)&Ol, g_Ol);
    cudaGetSymbolAddress((void**)&Wqh, g_Wqh); cudaGetSymbolAddress((void**)&Wql, g_Wql);
    cudaGetSymbolAddress((void**)&Wkh, g_Wkh); cudaGetSymbolAddress((void**)&Wkl, g_Wkl);
    cudaGetSymbolAddress((void**)&Wvh, g_Wvh); cudaGetSymbolAddress((void**)&Wvl, g_Wvl);
    cudaGetSymbolAddress((void**)&Woh, g_Woh); cudaGetSymbolAddress((void**)&Wol, g_Wol);

    // 1) embed (fused with X hi/lo split in TC cubin)
    embed_kernel<<<BT, 128>>>(tokens, tok_table, pos_emb);

    // 2) weight splits (no-op in fallback cubin); 2 rows per block
    split_tiles_kernel<<<EE / 2, 256>>>(Wq, Wqh, Wql);
    split_tiles_kernel<<<EE / 2, 256>>>(Wk, Wkh, Wkl);
    split_tiles_kernel<<<EE / 2, 256>>>(Wv, Wvh, Wvl);
    split_tiles_kernel<<<VV / 2, 256>>>(Wo, Woh, Wol);

    // 3) QKV projections — both paths (one is empty)
    gemm_tc<<<dim3(BT / 128, EE / 256), 128, GEMM_SMEM>>>(Xh, Xl, Wqh, Wql, bq, Q, EE);
    gemm_tc<<<dim3(BT / 128, EE / 256), 128, GEMM_SMEM>>>(Xh, Xl, Wkh, Wkl, bk, K, EE);
    gemm_tc<<<dim3(BT / 128, EE / 256), 128, GEMM_SMEM>>>(Xh, Xl, Wvh, Wvl, bv, V, EE);
    gemm_tf32<<<dim3(EE / 128, BT / 128), 256, TF_SMEM>>>(X, Wq, bq, Q, EE);
    gemm_tf32<<<dim3(EE / 128, BT / 128), 256, TF_SMEM>>>(X, Wk, bk, K, EE);
    gemm_tf32<<<dim3(EE / 128, BT / 128), 256, TF_SMEM>>>(X, Wv, bv, V, EE);

    // 4) attention (writes Oh/Ol tiles directly in TC cubin)
    attn_kernel<<<dim3(BB * HH, TT / 128), 128>>>();

    // 5) logits — both paths (one is empty)
    gemm_tc<<<dim3(BT / 128, VV / 256), 128, GEMM_SMEM>>>(Oh, Ol, Woh, Wol, bo, out, VV);
    gemm_tf32<<<dim3(VV / 128, BT / 128), 256, TF_SMEM>>>(O, Wo, bo, out, VV);

    // 6) loss
    row_loss_kernel<<<BT, 256>>>(out, targets);
    final_loss_kernel<<<1, 256>>>(out);
}